// round 2
// baseline (speedup 1.0000x reference)
#include <cuda_runtime.h>

// Problem constants (from reference): N=50000, D=128, E=625000
#define N_NODE   50000
#define D_FEAT   128
#define N_EDGE   625000
#define SIM_THRESH 0.1f

// Scratch (device globals — no allocation allowed in kernel_launch)
__device__ float g_inv_nrm[N_NODE];   // 1 / max(||f||, 1e-12)
__device__ float g_row_sum[N_NODE];   // L1 row sums of thresholded sim
__device__ float g_sim[N_EDGE];       // thresholded per-edge sim
__device__ int   g_idx_stride;        // 1 = int32 edge_index, 2 = int64 edge_index

// ---------------------------------------------------------------------------
// Kernel 0: detect edge_index dtype. If stored as int64 (little-endian) the
// odd 32-bit words of the first elements are all zero (indices < 50000).
// ---------------------------------------------------------------------------
__global__ void detect_kernel(const int* __restrict__ idx32) {
    bool all_hi_zero = true;
    #pragma unroll
    for (int i = 0; i < 8; i++)
        if (idx32[2 * i + 1] != 0) all_hi_zero = false;
    g_idx_stride = all_hi_zero ? 2 : 1;
}

__device__ __forceinline__ int load_idx(const int* idx32, long long pos, int stride) {
    return idx32[pos * stride];
}

// ---------------------------------------------------------------------------
// Kernel 1: per-node inverse norm (warp per node) + zero row_sum
// ---------------------------------------------------------------------------
__global__ void norm_kernel(const float* __restrict__ feat, int n_node) {
    int tid  = blockIdx.x * blockDim.x + threadIdx.x;
    int warp = tid >> 5;
    int lane = threadIdx.x & 31;

    if (tid < n_node) g_row_sum[tid] = 0.0f;
    if (warp >= n_node) return;

    const float4* fr = reinterpret_cast<const float4*>(feat + (size_t)warp * D_FEAT);
    float4 a = fr[lane];
    float s = a.x * a.x + a.y * a.y + a.z * a.z + a.w * a.w;
    #pragma unroll
    for (int off = 16; off > 0; off >>= 1)
        s += __shfl_xor_sync(0xFFFFFFFFu, s, off);

    if (lane == 0) {
        float nrm = sqrtf(s);
        g_inv_nrm[warp] = 1.0f / fmaxf(nrm, 1e-12f);
    }
}

// ---------------------------------------------------------------------------
// Kernel 2: per-edge cosine sim (warp per edge), threshold, atomic row sum
// ---------------------------------------------------------------------------
__global__ void sim_kernel(const int* __restrict__ ei,
                           const float* __restrict__ feat,
                           int n_edge) {
    int warp = (blockIdx.x * blockDim.x + threadIdx.x) >> 5;
    int lane = threadIdx.x & 31;
    if (warp >= n_edge) return;

    int stride = g_idx_stride;
    int r = load_idx(ei, warp, stride);
    int c = load_idx(ei, (long long)n_edge + warp, stride);

    const float4* fr = reinterpret_cast<const float4*>(feat + (size_t)r * D_FEAT);
    const float4* fc = reinterpret_cast<const float4*>(feat + (size_t)c * D_FEAT);
    float4 a = fr[lane];
    float4 b = fc[lane];
    float acc = a.x * b.x + a.y * b.y + a.z * b.z + a.w * b.w;
    #pragma unroll
    for (int off = 16; off > 0; off >>= 1)
        acc += __shfl_xor_sync(0xFFFFFFFFu, acc, off);

    if (lane == 0) {
        float s = acc * g_inv_nrm[r] * g_inv_nrm[c];
        s = (s < SIM_THRESH) ? 0.0f : s;
        g_sim[warp] = s;
        // after threshold s >= 0, so |s| == s; skip the zero adds
        if (s != 0.0f) atomicAdd(&g_row_sum[r], s);
    }
}

// ---------------------------------------------------------------------------
// Kernel 3: finish — normalize, exp, gate blend, clamp.
// (inputs guarantee row != col, so the lam/diagonal term is always zero)
// ---------------------------------------------------------------------------
__global__ void finish_kernel(const int* __restrict__ ei,
                              const float* __restrict__ edge_weight,
                              const float* __restrict__ gate,
                              float* __restrict__ out,
                              int n_edge) {
    int e = blockIdx.x * blockDim.x + threadIdx.x;
    if (e >= n_edge) return;

    int stride = g_idx_stride;
    int r = load_idx(ei, e, stride);
    float rs = g_row_sum[r];
    float denom = (rs > 0.0f) ? rs : 1.0f;
    float sn = g_sim[e] / denom;
    float att = expf(sn);
    float g = __ldg(gate);
    float v = g * edge_weight[e] + (1.0f - g) * att;
    out[e] = fmaxf(v, 0.0f);
}

// ---------------------------------------------------------------------------
extern "C" void kernel_launch(void* const* d_in, const int* in_sizes, int n_in,
                              void* d_out, int out_size) {
    const int*   ei   = (const int*)d_in[0];     // [2, E] int32 (or int64, detected)
    const float* ew   = (const float*)d_in[1];   // [E]
    const float* feat = (const float*)d_in[2];   // [N, D]
    const float* gate = (const float*)d_in[3];   // [1]

    int n_edge = in_sizes[1];
    int n_node = in_sizes[2] / D_FEAT;

    detect_kernel<<<1, 1>>>(ei);

    // Kernel 1: warp per node, 256 threads/block = 8 nodes/block
    {
        int blocks = (n_node * 32 + 255) / 256;
        norm_kernel<<<blocks, 256>>>(feat, n_node);
    }
    // Kernel 2: warp per edge
    {
        long long total = (long long)n_edge * 32;
        int blocks = (int)((total + 255) / 256);
        sim_kernel<<<blocks, 256>>>(ei, feat, n_edge);
    }
    // Kernel 3: thread per edge
    {
        int blocks = (n_edge + 255) / 256;
        finish_kernel<<<blocks, 256>>>(ei, ew, gate, (float*)d_out, n_edge);
    }
}